// round 1
// baseline (speedup 1.0000x reference)
#include <cuda_runtime.h>
#include <cuda_bf16.h>

// MixingBlock: out = (s, w) where
//   q = x@Wq, k = slot@Wk, dots = (q@k^T)*att_dim^-0.5, w = softmax(dots), s = w@slot
// Restructured: M[b] = scale * Wq @ (slot[b]@Wk)^T  is [180x32] per batch,
// so dots[b,r,:] = x[b,r,:] @ M[b]  -- the 18 GFLOP q GEMM is never needed.
//
// Shapes (fixed by the problem):
#define BB 4
#define RR 8192
#define SS 32
#define IN_DIM 180
#define SLOT_DIM 1536
#define ATT_DIM 1536
#define KSPLIT 4          // GEMM1 split over the j (slot_dim) reduction
#define KC (SLOT_DIM / KSPLIT)   // 384
#define TILE_R 32
#define DT 256            // d-tile width in fused epilogue

// Scratch (device globals; no allocation allowed)
__device__ float g_kpart[KSPLIT * BB * ATT_DIM * SS]; // [p][b][a][s], partial over j-chunk p
__device__ float g_Mpart[KSPLIT * BB * IN_DIM * SS];  // [p][b][i][s]

// ---------------------------------------------------------------------------
// GEMM1: g_kpart[p][b][a][s] = sum_{j in chunk p} slot[b][s][j] * Wk[j][a]
// Block tile: 32 rows (all s of one b) x 128 cols (a), K chunk 384, Kc=32.
// Grid (12, 4, 4) = 192 blocks, 256 threads, 4x4 microtile per thread.
// ---------------------------------------------------------------------------
__global__ __launch_bounds__(256) void gemm1_kernel(const float* __restrict__ slot,
                                                    const float* __restrict__ Wk) {
    __shared__ float As[32 * 36];   // [s][k], stride 36 (conflict-free reads)
    __shared__ float Bs[32 * 128];  // [k][c]
    int t = threadIdx.x;
    int warp = t >> 5, lane = t & 31;
    int a0 = blockIdx.x * 128;
    int b  = blockIdx.y;
    int p  = blockIdx.z;
    int j_base = p * KC;

    float acc[4][4] = {};
    for (int jc = 0; jc < KC / 32; jc++) {
        int j0 = j_base + jc * 32;
        // stage A: 32 s x 32 j
        {
            int s_l = t >> 3, k4 = (t & 7) << 2;
            float4 v = *reinterpret_cast<const float4*>(
                &slot[(size_t)(b * SS + s_l) * SLOT_DIM + j0 + k4]);
            *reinterpret_cast<float4*>(&As[s_l * 36 + k4]) = v;
        }
        // stage B: 32 j x 128 a
        {
            int k = t >> 3, cb = (t & 7) << 2;
            const float* src = &Wk[(size_t)(j0 + k) * ATT_DIM + a0];
            #pragma unroll
            for (int cc = 0; cc < 4; cc++) {
                int c = cb + cc * 32;
                *reinterpret_cast<float4*>(&Bs[k * 128 + c]) =
                    *reinterpret_cast<const float4*>(&src[c]);
            }
        }
        __syncthreads();
        #pragma unroll
        for (int k = 0; k < 32; k++) {
            float av[4];
            #pragma unroll
            for (int ri = 0; ri < 4; ri++) av[ri] = As[(4 * warp + ri) * 36 + k];
            float4 bv = *reinterpret_cast<const float4*>(&Bs[k * 128 + lane * 4]);
            #pragma unroll
            for (int ri = 0; ri < 4; ri++) {
                acc[ri][0] += av[ri] * bv.x;
                acc[ri][1] += av[ri] * bv.y;
                acc[ri][2] += av[ri] * bv.z;
                acc[ri][3] += av[ri] * bv.w;
            }
        }
        __syncthreads();
    }
    // store transposed to [a][s] so GEMM2 reads coalesced
    float* dst = &g_kpart[((size_t)(p * BB + b) * ATT_DIM + a0) * SS];
    #pragma unroll
    for (int ri = 0; ri < 4; ri++)
        #pragma unroll
        for (int ci = 0; ci < 4; ci++)
            dst[(lane * 4 + ci) * SS + 4 * warp + ri] = acc[ri][ci];
}

// ---------------------------------------------------------------------------
// GEMM2: g_Mpart[p][b][i][s] = sum_a Wq[i][a] * g_kpart[p][b][a][s]
// Block: 8 warps = 8 i's, smem-staged kpart chunks (64 a's at a time).
// Grid ((180+7)/8, 4, 4), 256 threads. Lanes own s.
// ---------------------------------------------------------------------------
__global__ __launch_bounds__(256) void gemm2_kernel(const float* __restrict__ Wq) {
    __shared__ float ks[64 * 32];   // [a_local][s]
    int t = threadIdx.x;
    int warp = t >> 5, lane = t & 31;
    int b = blockIdx.y, p = blockIdx.z;
    int i = blockIdx.x * 8 + warp;
    const float* kp = &g_kpart[(size_t)(p * BB + b) * ATT_DIM * SS];
    float acc = 0.f;
    for (int a0 = 0; a0 < ATT_DIM; a0 += 64) {
        __syncthreads();
        #pragma unroll
        for (int v = 0; v < 2; v++) {
            int lin = (t + v * 256) * 4;
            *reinterpret_cast<float4*>(&ks[lin]) =
                *reinterpret_cast<const float4*>(&kp[(size_t)a0 * SS + lin]);
        }
        __syncthreads();
        if (i < IN_DIM) {
            const float* wr = &Wq[(size_t)i * ATT_DIM + a0];
            #pragma unroll
            for (int aa = 0; aa < 64; aa += 4) {
                float4 w4 = *reinterpret_cast<const float4*>(&wr[aa]);
                acc += w4.x * ks[(aa + 0) * 32 + lane];
                acc += w4.y * ks[(aa + 1) * 32 + lane];
                acc += w4.z * ks[(aa + 2) * 32 + lane];
                acc += w4.w * ks[(aa + 3) * 32 + lane];
            }
        }
    }
    if (i < IN_DIM)
        g_Mpart[((size_t)(p * BB + b) * IN_DIM + i) * SS + lane] = acc;
}

// ---------------------------------------------------------------------------
// Fused: dots = x @ M[b]  (K=180) -> softmax over 32 slots -> s = w @ slot
// Block: 32 rows x one batch. Grid (256, 4), 256 threads.
// Dynamic smem: w_s[1024] | regionA{ phase1: Ms[5760]+xs[5760], phase3: slot_s[8192] }
// ---------------------------------------------------------------------------
__global__ __launch_bounds__(256) void fused_kernel(const float* __restrict__ x,
                                                    const float* __restrict__ slot,
                                                    float* __restrict__ out_s,
                                                    float* __restrict__ out_w) {
    extern __shared__ float sm[];
    float* w_s    = sm;                 // 32*32
    float* Ms     = sm + 1024;          // 180*32   (phase 1)
    float* xs     = sm + 1024 + 5760;   // 32*180   (phase 1)
    float* slot_s = sm + 1024;          // 32*256   (phase 3, overlaps Ms/xs)

    int t = threadIdx.x;
    int warp = t >> 5, lane = t & 31;
    int r0 = blockIdx.x * TILE_R;
    int b  = blockIdx.y;
    const float scale = rsqrtf((float)ATT_DIM);

    // load M[b] = scale * sum_p Mpart
    for (int idx = t; idx < IN_DIM * SS; idx += 256) {
        float v = 0.f;
        #pragma unroll
        for (int p = 0; p < KSPLIT; p++)
            v += g_Mpart[(size_t)(p * BB + b) * IN_DIM * SS + idx];
        Ms[idx] = v * scale;
    }
    // load x tile (32 x 180, row-contiguous, float4)
    {
        const float* xsrc = &x[(size_t)(b * RR + r0) * IN_DIM];
        for (int idx4 = t; idx4 < (TILE_R * IN_DIM) / 4; idx4 += 256)
            *reinterpret_cast<float4*>(&xs[idx4 * 4]) =
                *reinterpret_cast<const float4*>(&xsrc[idx4 * 4]);
    }
    __syncthreads();

    // phase 1: dots[r][s], thread owns (r = t>>3, s = (t&7)*4 .. +3)
    int r_l = t >> 3;
    int sg  = (t & 7) << 2;
    float d0 = 0.f, d1 = 0.f, d2 = 0.f, d3 = 0.f;
    const float* xrow = &xs[r_l * IN_DIM];
    #pragma unroll 4
    for (int i = 0; i < IN_DIM; i++) {
        float xv = xrow[i];
        float4 m4 = *reinterpret_cast<const float4*>(&Ms[i * SS + sg]);
        d0 += xv * m4.x; d1 += xv * m4.y; d2 += xv * m4.z; d3 += xv * m4.w;
    }
    // phase 2: softmax over s (8 lanes per row share via shfl within 8-lane groups)
    float mx = fmaxf(fmaxf(d0, d1), fmaxf(d2, d3));
    #pragma unroll
    for (int o = 1; o < 8; o <<= 1) mx = fmaxf(mx, __shfl_xor_sync(0xffffffffu, mx, o));
    d0 = __expf(d0 - mx); d1 = __expf(d1 - mx);
    d2 = __expf(d2 - mx); d3 = __expf(d3 - mx);
    float sum = d0 + d1 + d2 + d3;
    #pragma unroll
    for (int o = 1; o < 8; o <<= 1) sum += __shfl_xor_sync(0xffffffffu, sum, o);
    float inv = 1.0f / sum;
    d0 *= inv; d1 *= inv; d2 *= inv; d3 *= inv;
    float4 wv = make_float4(d0, d1, d2, d3);
    *reinterpret_cast<float4*>(&w_s[r_l * SS + sg]) = wv;
    *reinterpret_cast<float4*>(&out_w[(size_t)(b * RR + r0 + r_l) * SS + sg]) = wv;
    __syncthreads();   // Ms/xs reads done, w_s writes visible

    // phase 3: s = w @ slot.  Warp owns rows 4w..4w+3; lane owns cols lane*4 and 128+lane*4.
    float* outp = &out_s[(size_t)(b * RR + r0) * SLOT_DIM];
    for (int d0i = 0; d0i < SLOT_DIM; d0i += DT) {
        // stage slot[b][:, d0i:d0i+256] (32 x 256)
        for (int idx4 = t; idx4 < (SS * DT) / 4; idx4 += 256) {
            int s_i = idx4 / (DT / 4);
            int c4  = idx4 % (DT / 4);
            *reinterpret_cast<float4*>(&slot_s[s_i * DT + c4 * 4]) =
                *reinterpret_cast<const float4*>(
                    &slot[(size_t)(b * SS + s_i) * SLOT_DIM + d0i + c4 * 4]);
        }
        __syncthreads();
        float acc[4][8] = {};
        const float* wrow = &w_s[(4 * warp) * SS];
        #pragma unroll
        for (int s_i = 0; s_i < SS; s_i++) {
            float w0 = wrow[s_i];
            float w1 = wrow[SS + s_i];
            float w2 = wrow[2 * SS + s_i];
            float w3 = wrow[3 * SS + s_i];
            float4 v0 = *reinterpret_cast<const float4*>(&slot_s[s_i * DT + lane * 4]);
            float4 v1 = *reinterpret_cast<const float4*>(&slot_s[s_i * DT + 128 + lane * 4]);
            acc[0][0] += w0 * v0.x; acc[0][1] += w0 * v0.y; acc[0][2] += w0 * v0.z; acc[0][3] += w0 * v0.w;
            acc[0][4] += w0 * v1.x; acc[0][5] += w0 * v1.y; acc[0][6] += w0 * v1.z; acc[0][7] += w0 * v1.w;
            acc[1][0] += w1 * v0.x; acc[1][1] += w1 * v0.y; acc[1][2] += w1 * v0.z; acc[1][3] += w1 * v0.w;
            acc[1][4] += w1 * v1.x; acc[1][5] += w1 * v1.y; acc[1][6] += w1 * v1.z; acc[1][7] += w1 * v1.w;
            acc[2][0] += w2 * v0.x; acc[2][1] += w2 * v0.y; acc[2][2] += w2 * v0.z; acc[2][3] += w2 * v0.w;
            acc[2][4] += w2 * v1.x; acc[2][5] += w2 * v1.y; acc[2][6] += w2 * v1.z; acc[2][7] += w2 * v1.w;
            acc[3][0] += w3 * v0.x; acc[3][1] += w3 * v0.y; acc[3][2] += w3 * v0.z; acc[3][3] += w3 * v0.w;
            acc[3][4] += w3 * v1.x; acc[3][5] += w3 * v1.y; acc[3][6] += w3 * v1.z; acc[3][7] += w3 * v1.w;
        }
        #pragma unroll
        for (int ri = 0; ri < 4; ri++) {
            float4 o0 = make_float4(acc[ri][0], acc[ri][1], acc[ri][2], acc[ri][3]);
            float4 o1 = make_float4(acc[ri][4], acc[ri][5], acc[ri][6], acc[ri][7]);
            float* orow = &outp[(size_t)(4 * warp + ri) * SLOT_DIM + d0i];
            *reinterpret_cast<float4*>(&orow[lane * 4]) = o0;
            *reinterpret_cast<float4*>(&orow[128 + lane * 4]) = o1;
        }
        __syncthreads();
    }
}

// ---------------------------------------------------------------------------
extern "C" void kernel_launch(void* const* d_in, const int* in_sizes, int n_in,
                              void* d_out, int out_size) {
    const float* x    = (const float*)d_in[0];  // [4, 8192, 180]
    const float* slot = (const float*)d_in[1];  // [4, 32, 1536]
    const float* Wq   = (const float*)d_in[2];  // [180, 1536]
    const float* Wk   = (const float*)d_in[3];  // [1536, 1536]
    float* out_s = (float*)d_out;                                   // [4, 8192, 1536]
    float* out_w = out_s + (size_t)BB * RR * ATT_DIM;               // [4, 8192, 32]

    const int smem_bytes = (1024 + 5760 + 5760) * 4;  // 50176 > 48KB static limit
    cudaFuncSetAttribute(fused_kernel, cudaFuncAttributeMaxDynamicSharedMemorySize, smem_bytes);

    gemm1_kernel<<<dim3(ATT_DIM / 128, BB, KSPLIT), 256>>>(slot, Wk);
    gemm2_kernel<<<dim3((IN_DIM + 7) / 8, BB, KSPLIT), 256>>>(Wq);
    fused_kernel<<<dim3(RR / TILE_R, BB), 256, smem_bytes>>>(x, slot, out_s, out_w);
}

// round 2
// speedup vs baseline: 1.1171x; 1.1171x over previous
#include <cuda_runtime.h>
#include <cuda_bf16.h>

// MixingBlock restructured:
//   M[b] = scale * Wq @ (slot[b]@Wk)^T   [180 x 32] per batch
//   dots[b,r,:] = x[b,r,:] @ M[b] ; w = softmax(dots); s = w @ slot[b]
// All fp32, with packed f32x2 FMA (Blackwell FFMA2) in the hot loops.

#define BB 4
#define RR 8192
#define SS 32
#define IN_DIM 180
#define SLOT_DIM 1536
#define ATT_DIM 1536
#define KSPLIT 8                  // gemm1 split over slot_dim reduction
#define KC (SLOT_DIM / KSPLIT)    // 192
#define ASPLIT 4                  // gemm2 split over att_dim reduction
#define AC (ATT_DIM / ASPLIT)     // 384
#define TILE_R 64
#define DT 128

typedef unsigned long long u64;

__device__ __forceinline__ u64 fma2(u64 a, u64 b, u64 c) {
    u64 d;
    asm("fma.rn.f32x2 %0, %1, %2, %3;" : "=l"(d) : "l"(a), "l"(b), "l"(c));
    return d;
}
__device__ __forceinline__ u64 pk2(float v) {
    u64 r;
    asm("mov.b64 %0, {%1, %1};" : "=l"(r) : "r"(__float_as_uint(v)));
    return r;
}

// Scratch
__device__ float g_kpart[KSPLIT * BB * ATT_DIM * SS];  // [p][b][a][s]
__device__ float g_ksum[BB * ATT_DIM * SS];            // [b][a][s]
__device__ float g_Mpart[ASPLIT * BB * IN_DIM * SS];   // [p2][b][i][s]

// ---------------------------------------------------------------------------
// GEMM1: g_kpart[p][b][a][s] = sum_{j in chunk p} slot[b][s][j] * Wk[j][a]
// Grid (12, 4, 8) = 384 blocks, 256 threads, f32x2 microtile 4 rows x 4 cols.
// ---------------------------------------------------------------------------
__global__ __launch_bounds__(256) void gemm1_kernel(const float* __restrict__ slot,
                                                    const float* __restrict__ Wk) {
    __shared__ float As[32 * 36];   // [s][k], stride 36
    __shared__ float Bs[32 * 128];  // [k][c]
    int t = threadIdx.x;
    int warp = t >> 5, lane = t & 31;
    int a0 = blockIdx.x * 128;
    int b  = blockIdx.y;
    int p  = blockIdx.z;
    int j_base = p * KC;

    u64 acc[4][2] = {};
    for (int jc = 0; jc < KC / 32; jc++) {
        int j0 = j_base + jc * 32;
        {   // stage A: 32 s x 32 j
            int s_l = t >> 3, k4 = (t & 7) << 2;
            float4 v = *reinterpret_cast<const float4*>(
                &slot[(size_t)(b * SS + s_l) * SLOT_DIM + j0 + k4]);
            *reinterpret_cast<float4*>(&As[s_l * 36 + k4]) = v;
        }
        {   // stage B: 32 j x 128 a
            int k = t >> 3, cb = (t & 7) << 2;
            const float* src = &Wk[(size_t)(j0 + k) * ATT_DIM + a0];
            #pragma unroll
            for (int cc = 0; cc < 4; cc++) {
                int c = cb + cc * 32;
                *reinterpret_cast<float4*>(&Bs[k * 128 + c]) =
                    *reinterpret_cast<const float4*>(&src[c]);
            }
        }
        __syncthreads();
        #pragma unroll 8
        for (int k = 0; k < 32; k++) {
            ulonglong2 bv = *reinterpret_cast<const ulonglong2*>(&Bs[k * 128 + lane * 4]);
            #pragma unroll
            for (int ri = 0; ri < 4; ri++) {
                u64 a2 = pk2(As[(4 * warp + ri) * 36 + k]);
                acc[ri][0] = fma2(a2, bv.x, acc[ri][0]);
                acc[ri][1] = fma2(a2, bv.y, acc[ri][1]);
            }
        }
        __syncthreads();
    }
    // store transposed to [a][s]
    float* dst = &g_kpart[((size_t)(p * BB + b) * ATT_DIM + a0) * SS];
    #pragma unroll
    for (int ri = 0; ri < 4; ri++) {
        #pragma unroll
        for (int cj = 0; cj < 2; cj++) {
            float lo = __uint_as_float((unsigned)(acc[ri][cj] & 0xffffffffu));
            float hi = __uint_as_float((unsigned)(acc[ri][cj] >> 32));
            dst[(lane * 4 + 2 * cj + 0) * SS + 4 * warp + ri] = lo;
            dst[(lane * 4 + 2 * cj + 1) * SS + 4 * warp + ri] = hi;
        }
    }
}

// ---------------------------------------------------------------------------
// Reduce: g_ksum = sum_p g_kpart    (196608 floats; L2-resident)
// ---------------------------------------------------------------------------
__global__ __launch_bounds__(256) void reducek_kernel() {
    int idx = blockIdx.x * 256 + threadIdx.x;  // float4 index, grid covers 49152
    const float4* src = reinterpret_cast<const float4*>(g_kpart);
    float4 a = src[idx];
    #pragma unroll
    for (int p = 1; p < KSPLIT; p++) {
        float4 v = src[(size_t)p * (BB * ATT_DIM * SS / 4) + idx];
        a.x += v.x; a.y += v.y; a.z += v.z; a.w += v.w;
    }
    reinterpret_cast<float4*>(g_ksum)[idx] = a;
}

// ---------------------------------------------------------------------------
// GEMM2: g_Mpart[p2][b][i][s] = sum_{a in chunk p2} Wq[i][a] * g_ksum[b][a][s]
// Grid (23, 4, 4), 256 threads; warp owns one i, lanes own s.
// ---------------------------------------------------------------------------
__global__ __launch_bounds__(256) void gemm2_kernel(const float* __restrict__ Wq) {
    __shared__ float ks[64 * 32];
    int t = threadIdx.x;
    int warp = t >> 5, lane = t & 31;
    int b = blockIdx.y, p2 = blockIdx.z;
    int i = blockIdx.x * 8 + warp;
    const float* kp = &g_ksum[(size_t)b * ATT_DIM * SS];
    int a_lo = p2 * AC;
    float acc = 0.f;
    for (int a0 = a_lo; a0 < a_lo + AC; a0 += 64) {
        __syncthreads();
        #pragma unroll
        for (int v = 0; v < 2; v++) {
            int lin = (t + v * 256) * 4;
            *reinterpret_cast<float4*>(&ks[lin]) =
                *reinterpret_cast<const float4*>(&kp[(size_t)a0 * SS + lin]);
        }
        __syncthreads();
        if (i < IN_DIM) {
            const float* wr = &Wq[(size_t)i * ATT_DIM + a0];
            #pragma unroll
            for (int aa = 0; aa < 64; aa += 4) {
                float4 w4 = *reinterpret_cast<const float4*>(&wr[aa]);
                acc += w4.x * ks[(aa + 0) * 32 + lane];
                acc += w4.y * ks[(aa + 1) * 32 + lane];
                acc += w4.z * ks[(aa + 2) * 32 + lane];
                acc += w4.w * ks[(aa + 3) * 32 + lane];
            }
        }
    }
    if (i < IN_DIM)
        g_Mpart[((size_t)(p2 * BB + b) * IN_DIM + i) * SS + lane] = acc;
}

// ---------------------------------------------------------------------------
// Fused: dots = x@M -> softmax -> s = w@slot.  64 rows per block, f32x2 math.
// Static smem layout (47616 B):
//   [0, 16384)      u64 w2t[32][64]   packed (w,w), transposed [s][r]
//   [16384, 24576)  float dots[64][32]
//   [24576, 47616)  float Ms[180][32]  (phase 1)  /  float slot_s[32][128] (phase 3)
// ---------------------------------------------------------------------------
__global__ __launch_bounds__(256) void fused_kernel(const float* __restrict__ x,
                                                    const float* __restrict__ slot,
                                                    float* __restrict__ out_s,
                                                    float* __restrict__ out_w) {
    __shared__ __align__(16) char smraw[47616];
    u64*   w2t    = reinterpret_cast<u64*>(smraw);            // [s][64]
    float* dots_s = reinterpret_cast<float*>(smraw + 16384);  // [r][32]
    float* Ms     = reinterpret_cast<float*>(smraw + 24576);  // [i][32]
    float* slot_s = Ms;                                       // [s][128]

    int t = threadIdx.x;
    int warp = t >> 5, lane = t & 31;
    int r0 = blockIdx.x * TILE_R;
    int b  = blockIdx.y;
    const float scale = rsqrtf((float)ATT_DIM);

    // Load M[b] = scale * sum_{p2} Mpart
    for (int idx = t; idx < IN_DIM * SS; idx += 256) {
        float v = 0.f;
        #pragma unroll
        for (int p2 = 0; p2 < ASPLIT; p2++)
            v += g_Mpart[(size_t)(p2 * BB + b) * IN_DIM * SS + idx];
        Ms[idx] = v * scale;
    }
    __syncthreads();

    // phase 1: dots; thread owns 4 rows x 2 s (one f32x2 per row)
    {
        int s2 = (t & 15) * 2;
        int rb = (t >> 4) * 4;
        const float* xbase = &x[(size_t)(b * RR + r0 + rb) * IN_DIM];
        u64 d2[4] = {0ull, 0ull, 0ull, 0ull};
        for (int i4 = 0; i4 < IN_DIM / 4; i4++) {
            float4 xv[4];
            #pragma unroll
            for (int j = 0; j < 4; j++)
                xv[j] = *reinterpret_cast<const float4*>(&xbase[(size_t)j * IN_DIM + i4 * 4]);
            #pragma unroll
            for (int c = 0; c < 4; c++) {
                u64 m2 = *reinterpret_cast<const u64*>(&Ms[(i4 * 4 + c) * SS + s2]);
                const float* xc;
                #pragma unroll
                for (int j = 0; j < 4; j++) {
                    xc = reinterpret_cast<const float*>(&xv[j]);
                    d2[j] = fma2(pk2(xc[c]), m2, d2[j]);
                }
            }
        }
        #pragma unroll
        for (int j = 0; j < 4; j++)
            *reinterpret_cast<u64*>(&dots_s[(rb + j) * SS + s2]) = d2[j];
    }
    __syncthreads();

    // phase 2: softmax; thread owns 1 row x 8 s, reduce over 4-lane groups
    {
        int r = t >> 2;
        int sg = (t & 3) * 8;
        float v[8];
        float4 a0 = *reinterpret_cast<const float4*>(&dots_s[r * SS + sg]);
        float4 a1 = *reinterpret_cast<const float4*>(&dots_s[r * SS + sg + 4]);
        v[0] = a0.x; v[1] = a0.y; v[2] = a0.z; v[3] = a0.w;
        v[4] = a1.x; v[5] = a1.y; v[6] = a1.z; v[7] = a1.w;
        float mx = v[0];
        #pragma unroll
        for (int k = 1; k < 8; k++) mx = fmaxf(mx, v[k]);
        mx = fmaxf(mx, __shfl_xor_sync(0xffffffffu, mx, 1));
        mx = fmaxf(mx, __shfl_xor_sync(0xffffffffu, mx, 2));
        float sum = 0.f;
        #pragma unroll
        for (int k = 0; k < 8; k++) { v[k] = __expf(v[k] - mx); sum += v[k]; }
        sum += __shfl_xor_sync(0xffffffffu, sum, 1);
        sum += __shfl_xor_sync(0xffffffffu, sum, 2);
        float inv = 1.0f / sum;
        #pragma unroll
        for (int k = 0; k < 8; k++) v[k] *= inv;
        // out_w
        float* wp = &out_w[(size_t)(b * RR + r0 + r) * SS + sg];
        *reinterpret_cast<float4*>(&wp[0]) = make_float4(v[0], v[1], v[2], v[3]);
        *reinterpret_cast<float4*>(&wp[4]) = make_float4(v[4], v[5], v[6], v[7]);
        // packed transposed w2t[s][r]
        #pragma unroll
        for (int k = 0; k < 8; k++)
            w2t[(sg + k) * TILE_R + r] = pk2(v[k]);
    }
    __syncthreads();

    // phase 3: s = w @ slot ; warp owns 8 rows, lane owns 4 cols (2 f32x2)
    int rw = warp * 8;
    float* outp = &out_s[(size_t)(b * RR + r0) * SLOT_DIM];
    for (int dt = 0; dt < SLOT_DIM / DT; dt++) {
        // stage slot[b][:, dt*128 .. +128)
        #pragma unroll
        for (int it = 0; it < 4; it++) {
            int idx4 = t + it * 256;
            int row = idx4 >> 5;
            int c4  = idx4 & 31;
            *reinterpret_cast<float4*>(&slot_s[row * DT + c4 * 4]) =
                *reinterpret_cast<const float4*>(
                    &slot[(size_t)(b * SS + row) * SLOT_DIM + dt * DT + c4 * 4]);
        }
        __syncthreads();
        u64 acc[8][2] = {};
        #pragma unroll 8
        for (int s = 0; s < SS; s++) {
            ulonglong2 vv = *reinterpret_cast<const ulonglong2*>(&slot_s[s * DT + lane * 4]);
            const u64* wr = &w2t[s * TILE_R + rw];
            #pragma unroll
            for (int j = 0; j < 8; j += 2) {
                ulonglong2 w2 = *reinterpret_cast<const ulonglong2*>(&wr[j]);
                acc[j][0]     = fma2(w2.x, vv.x, acc[j][0]);
                acc[j][1]     = fma2(w2.x, vv.y, acc[j][1]);
                acc[j + 1][0] = fma2(w2.y, vv.x, acc[j + 1][0]);
                acc[j + 1][1] = fma2(w2.y, vv.y, acc[j + 1][1]);
            }
        }
        #pragma unroll
        for (int j = 0; j < 8; j++) {
            ulonglong2 o; o.x = acc[j][0]; o.y = acc[j][1];
            *reinterpret_cast<ulonglong2*>(
                &outp[(size_t)(rw + j) * SLOT_DIM + dt * DT + lane * 4]) = o;
        }
        __syncthreads();
    }
}

// ---------------------------------------------------------------------------
extern "C" void kernel_launch(void* const* d_in, const int* in_sizes, int n_in,
                              void* d_out, int out_size) {
    const float* x    = (const float*)d_in[0];  // [4, 8192, 180]
    const float* slot = (const float*)d_in[1];  // [4, 32, 1536]
    const float* Wq   = (const float*)d_in[2];  // [180, 1536]
    const float* Wk   = (const float*)d_in[3];  // [1536, 1536]
    float* out_s = (float*)d_out;                        // [4, 8192, 1536]
    float* out_w = out_s + (size_t)BB * RR * ATT_DIM;    // [4, 8192, 32]

    gemm1_kernel<<<dim3(ATT_DIM / 128, BB, KSPLIT), 256>>>(slot, Wk);
    reducek_kernel<<<(BB * ATT_DIM * SS / 4) / 256, 256>>>();
    gemm2_kernel<<<dim3((IN_DIM + 7) / 8, BB, ASPLIT), 256>>>(Wq);
    fused_kernel<<<dim3(RR / TILE_R, BB), 256>>>(x, slot, out_s, out_w);
}

// round 3
// speedup vs baseline: 1.1418x; 1.0221x over previous
#include <cuda_runtime.h>
#include <cuda_bf16.h>

// MixingBlock restructured:
//   M[b] = scale * Wq @ (slot[b]@Wk)^T   [180 x 32] per batch
//   dots[b,r,:] = x[b,r,:] @ M[b] ; w = softmax(dots); s = w @ slot[b]
// All fp32, packed f32x2 FMA (Blackwell FFMA2) in hot loops.

#define BB 4
#define RR 8192
#define SS 32
#define IN_DIM 180
#define SLOT_DIM 1536
#define ATT_DIM 1536
#define KSPLIT 16                 // gemm1 split over slot_dim reduction
#define KC (SLOT_DIM / KSPLIT)    // 96
#define ASPLIT 4                  // gemm2 split over att_dim reduction
#define AC (ATT_DIM / ASPLIT)     // 384
#define TILE_R 64
#define DT 256

typedef unsigned long long u64;

__device__ __forceinline__ u64 fma2(u64 a, u64 b, u64 c) {
    u64 d;
    asm("fma.rn.f32x2 %0, %1, %2, %3;" : "=l"(d) : "l"(a), "l"(b), "l"(c));
    return d;
}
__device__ __forceinline__ u64 pk2(float v) {
    u64 r;
    asm("mov.b64 %0, {%1, %1};" : "=l"(r) : "r"(__float_as_uint(v)));
    return r;
}

// Scratch
__device__ float g_kpart[KSPLIT * BB * ATT_DIM * SS];  // [p][b][a][s]
__device__ float g_ksum[BB * ATT_DIM * SS];            // [b][a][s]
__device__ float g_Mpart[ASPLIT * BB * IN_DIM * SS];   // [p2][b][i][s]

// ---------------------------------------------------------------------------
// GEMM1: g_kpart[p][b][a][s] = sum_{j in chunk p} slot[b][s][j] * Wk[j][a]
// Grid (12, 4, 16) = 768 blocks, 256 threads, f32x2 microtile 4r x 4c.
// ---------------------------------------------------------------------------
__global__ __launch_bounds__(256) void gemm1_kernel(const float* __restrict__ slot,
                                                    const float* __restrict__ Wk) {
    __shared__ float As[32 * 36];   // [s][k], stride 36
    __shared__ float Bs[32 * 128];  // [k][c]
    int t = threadIdx.x;
    int warp = t >> 5, lane = t & 31;
    int a0 = blockIdx.x * 128;
    int b  = blockIdx.y;
    int p  = blockIdx.z;
    int j_base = p * KC;

    u64 acc[4][2] = {};
    for (int jc = 0; jc < KC / 32; jc++) {
        int j0 = j_base + jc * 32;
        {   // stage A: 32 s x 32 j
            int s_l = t >> 3, k4 = (t & 7) << 2;
            float4 v = *reinterpret_cast<const float4*>(
                &slot[(size_t)(b * SS + s_l) * SLOT_DIM + j0 + k4]);
            *reinterpret_cast<float4*>(&As[s_l * 36 + k4]) = v;
        }
        {   // stage B: 32 j x 128 a
            int k = t >> 3, cb = (t & 7) << 2;
            const float* src = &Wk[(size_t)(j0 + k) * ATT_DIM + a0];
            #pragma unroll
            for (int cc = 0; cc < 4; cc++) {
                int c = cb + cc * 32;
                *reinterpret_cast<float4*>(&Bs[k * 128 + c]) =
                    *reinterpret_cast<const float4*>(&src[c]);
            }
        }
        __syncthreads();
        #pragma unroll 8
        for (int k = 0; k < 32; k++) {
            ulonglong2 bv = *reinterpret_cast<const ulonglong2*>(&Bs[k * 128 + lane * 4]);
            #pragma unroll
            for (int ri = 0; ri < 4; ri++) {
                u64 a2 = pk2(As[(4 * warp + ri) * 36 + k]);
                acc[ri][0] = fma2(a2, bv.x, acc[ri][0]);
                acc[ri][1] = fma2(a2, bv.y, acc[ri][1]);
            }
        }
        __syncthreads();
    }
    float* dst = &g_kpart[((size_t)(p * BB + b) * ATT_DIM + a0) * SS];
    #pragma unroll
    for (int ri = 0; ri < 4; ri++) {
        #pragma unroll
        for (int cj = 0; cj < 2; cj++) {
            float lo = __uint_as_float((unsigned)(acc[ri][cj] & 0xffffffffu));
            float hi = __uint_as_float((unsigned)(acc[ri][cj] >> 32));
            dst[(lane * 4 + 2 * cj + 0) * SS + 4 * warp + ri] = lo;
            dst[(lane * 4 + 2 * cj + 1) * SS + 4 * warp + ri] = hi;
        }
    }
}

// ---------------------------------------------------------------------------
// Reduce: g_ksum = sum_p g_kpart
// ---------------------------------------------------------------------------
__global__ __launch_bounds__(256) void reducek_kernel() {
    int idx = blockIdx.x * 256 + threadIdx.x;  // float4 index over 49152
    const float4* src = reinterpret_cast<const float4*>(g_kpart);
    float4 a = src[idx];
    #pragma unroll
    for (int p = 1; p < KSPLIT; p++) {
        float4 v = src[(size_t)p * (BB * ATT_DIM * SS / 4) + idx];
        a.x += v.x; a.y += v.y; a.z += v.z; a.w += v.w;
    }
    reinterpret_cast<float4*>(g_ksum)[idx] = a;
}

// ---------------------------------------------------------------------------
// GEMM2: g_Mpart[p2][b][i][s] = sum_{a in chunk p2} Wq[i][a] * g_ksum[b][a][s]
// ---------------------------------------------------------------------------
__global__ __launch_bounds__(256) void gemm2_kernel(const float* __restrict__ Wq) {
    __shared__ float ks[64 * 32];
    int t = threadIdx.x;
    int warp = t >> 5, lane = t & 31;
    int b = blockIdx.y, p2 = blockIdx.z;
    int i = blockIdx.x * 8 + warp;
    const float* kp = &g_ksum[(size_t)b * ATT_DIM * SS];
    int a_lo = p2 * AC;
    float acc = 0.f;
    for (int a0 = a_lo; a0 < a_lo + AC; a0 += 64) {
        __syncthreads();
        #pragma unroll
        for (int v = 0; v < 2; v++) {
            int lin = (t + v * 256) * 4;
            *reinterpret_cast<float4*>(&ks[lin]) =
                *reinterpret_cast<const float4*>(&kp[(size_t)a0 * SS + lin]);
        }
        __syncthreads();
        if (i < IN_DIM) {
            const float* wr = &Wq[(size_t)i * ATT_DIM + a0];
            #pragma unroll
            for (int aa = 0; aa < 64; aa += 4) {
                float4 w4 = *reinterpret_cast<const float4*>(&wr[aa]);
                acc += w4.x * ks[(aa + 0) * 32 + lane];
                acc += w4.y * ks[(aa + 1) * 32 + lane];
                acc += w4.z * ks[(aa + 2) * 32 + lane];
                acc += w4.w * ks[(aa + 3) * 32 + lane];
            }
        }
    }
    if (i < IN_DIM)
        g_Mpart[((size_t)(p2 * BB + b) * IN_DIM + i) * SS + lane] = acc;
}

// ---------------------------------------------------------------------------
// Fused: dots = x@M -> softmax -> s = w@slot.  64 rows/block, 256 thr, 2 blk/SM.
// Static smem (49152 B exactly):
//   [0, 16384)      u64 w2t[32][64]     packed (w,w), transposed [s][r]
//   [16384, 49152)  float slot_s[32][256]        (phase 3)
//     phase-1 overlay: Ms[180][32] at 16384 (23040 B), dots[64][32] at 39424 (8192 B)
// ---------------------------------------------------------------------------
__global__ __launch_bounds__(256, 2) void fused_kernel(const float* __restrict__ x,
                                                       const float* __restrict__ slot,
                                                       float* __restrict__ out_s,
                                                       float* __restrict__ out_w) {
    __shared__ __align__(16) char smraw[49152];
    u64*   w2t    = reinterpret_cast<u64*>(smraw);            // [s][64]
    float* slot_s = reinterpret_cast<float*>(smraw + 16384);  // [s][256]
    float* Ms     = reinterpret_cast<float*>(smraw + 16384);  // [i][32]
    float* dots_s = reinterpret_cast<float*>(smraw + 39424);  // [r][32]

    int t = threadIdx.x;
    int warp = t >> 5, lane = t & 31;
    int r0 = blockIdx.x * TILE_R;
    int b  = blockIdx.y;
    const float scale = rsqrtf((float)ATT_DIM);

    // Load M[b] = scale * sum_{p2} Mpart
    for (int idx = t; idx < IN_DIM * SS; idx += 256) {
        float v = 0.f;
        #pragma unroll
        for (int p2 = 0; p2 < ASPLIT; p2++)
            v += g_Mpart[(size_t)(p2 * BB + b) * IN_DIM * SS + idx];
        Ms[idx] = v * scale;
    }
    __syncthreads();

    // phase 1: dots; thread owns 1 row x 8 s. sgroup = t&3, row = t>>2.
    {
        int sg = (t & 3) * 8;
        int r  = t >> 2;
        const float* xrow = &x[(size_t)(b * RR + r0 + r) * IN_DIM];
        u64 d2[4] = {0ull, 0ull, 0ull, 0ull};
        #pragma unroll 3
        for (int i4 = 0; i4 < IN_DIM / 4; i4++) {
            float4 xv = *reinterpret_cast<const float4*>(&xrow[i4 * 4]);
            const float* xc = reinterpret_cast<const float*>(&xv);
            #pragma unroll
            for (int c = 0; c < 4; c++) {
                int i = i4 * 4 + c;
                ulonglong2 m01 = *reinterpret_cast<const ulonglong2*>(&Ms[i * SS + sg]);
                ulonglong2 m23 = *reinterpret_cast<const ulonglong2*>(&Ms[i * SS + sg + 4]);
                u64 xp = pk2(xc[c]);
                d2[0] = fma2(xp, m01.x, d2[0]);
                d2[1] = fma2(xp, m01.y, d2[1]);
                d2[2] = fma2(xp, m23.x, d2[2]);
                d2[3] = fma2(xp, m23.y, d2[3]);
            }
        }
        ulonglong2 o0; o0.x = d2[0]; o0.y = d2[1];
        ulonglong2 o1; o1.x = d2[2]; o1.y = d2[3];
        *reinterpret_cast<ulonglong2*>(&dots_s[r * SS + sg]) = o0;
        *reinterpret_cast<ulonglong2*>(&dots_s[r * SS + sg + 4]) = o1;
    }
    __syncthreads();

    // phase 2: softmax; thread owns 1 row x 8 s, reduce over 4-lane groups.
    {
        int r = t >> 2;
        int sg = (t & 3) * 8;
        float v[8];
        float4 a0 = *reinterpret_cast<const float4*>(&dots_s[r * SS + sg]);
        float4 a1 = *reinterpret_cast<const float4*>(&dots_s[r * SS + sg + 4]);
        v[0] = a0.x; v[1] = a0.y; v[2] = a0.z; v[3] = a0.w;
        v[4] = a1.x; v[5] = a1.y; v[6] = a1.z; v[7] = a1.w;
        float mx = v[0];
        #pragma unroll
        for (int k = 1; k < 8; k++) mx = fmaxf(mx, v[k]);
        mx = fmaxf(mx, __shfl_xor_sync(0xffffffffu, mx, 1));
        mx = fmaxf(mx, __shfl_xor_sync(0xffffffffu, mx, 2));
        float sum = 0.f;
        #pragma unroll
        for (int k = 0; k < 8; k++) { v[k] = __expf(v[k] - mx); sum += v[k]; }
        sum += __shfl_xor_sync(0xffffffffu, sum, 1);
        sum += __shfl_xor_sync(0xffffffffu, sum, 2);
        float inv = 1.0f / sum;
        #pragma unroll
        for (int k = 0; k < 8; k++) v[k] *= inv;
        float* wp = &out_w[(size_t)(b * RR + r0 + r) * SS + sg];
        *reinterpret_cast<float4*>(&wp[0]) = make_float4(v[0], v[1], v[2], v[3]);
        *reinterpret_cast<float4*>(&wp[4]) = make_float4(v[4], v[5], v[6], v[7]);
        #pragma unroll
        for (int k = 0; k < 8; k++)
            w2t[(sg + k) * TILE_R + r] = pk2(v[k]);
    }

    // phase 3: s = w @ slot. Warp owns 8 rows; lane owns cols {lane*4, 128+lane*4}.
    int rw = warp * 8;
    float* outp = &out_s[(size_t)(b * RR + r0) * SLOT_DIM];
    for (int dt = 0; dt < SLOT_DIM / DT; dt++) {
        __syncthreads();   // prev-iter reads done (first iter: dots/Ms reads done)
        // stage slot[b][:, dt*256 .. +256): 2048 float4, 8 per thread
        #pragma unroll
        for (int it = 0; it < 8; it++) {
            int idx4 = t + it * 256;
            int row = idx4 >> 6;
            int c4  = idx4 & 63;
            *reinterpret_cast<float4*>(&slot_s[row * DT + c4 * 4]) =
                *reinterpret_cast<const float4*>(
                    &slot[(size_t)(b * SS + row) * SLOT_DIM + dt * DT + c4 * 4]);
        }
        __syncthreads();
        u64 acc[8][4] = {};
        #pragma unroll 4
        for (int s = 0; s < SS; s++) {
            const float* vbase = &slot_s[s * DT];
            ulonglong2 v0 = *reinterpret_cast<const ulonglong2*>(&vbase[lane * 4]);
            ulonglong2 v1 = *reinterpret_cast<const ulonglong2*>(&vbase[128 + lane * 4]);
            const u64* wr = &w2t[s * TILE_R + rw];
            #pragma unroll
            for (int jp = 0; jp < 4; jp++) {
                ulonglong2 w2 = *reinterpret_cast<const ulonglong2*>(&wr[2 * jp]);
                int j = 2 * jp;
                acc[j][0]     = fma2(w2.x, v0.x, acc[j][0]);
                acc[j][1]     = fma2(w2.x, v0.y, acc[j][1]);
                acc[j][2]     = fma2(w2.x, v1.x, acc[j][2]);
                acc[j][3]     = fma2(w2.x, v1.y, acc[j][3]);
                acc[j + 1][0] = fma2(w2.y, v0.x, acc[j + 1][0]);
                acc[j + 1][1] = fma2(w2.y, v0.y, acc[j + 1][1]);
                acc[j + 1][2] = fma2(w2.y, v1.x, acc[j + 1][2]);
                acc[j + 1][3] = fma2(w2.y, v1.y, acc[j + 1][3]);
            }
        }
        #pragma unroll
        for (int j = 0; j < 8; j++) {
            float* orow = &outp[(size_t)(rw + j) * SLOT_DIM + dt * DT];
            ulonglong2 o0; o0.x = acc[j][0]; o0.y = acc[j][1];
            ulonglong2 o1; o1.x = acc[j][2]; o1.y = acc[j][3];
            *reinterpret_cast<ulonglong2*>(&orow[lane * 4]) = o0;
            *reinterpret_cast<ulonglong2*>(&orow[128 + lane * 4]) = o1;
        }
    }
}

// ---------------------------------------------------------------------------
extern "C" void kernel_launch(void* const* d_in, const int* in_sizes, int n_in,
                              void* d_out, int out_size) {
    const float* x    = (const float*)d_in[0];  // [4, 8192, 180]
    const float* slot = (const float*)d_in[1];  // [4, 32, 1536]
    const float* Wq   = (const float*)d_in[2];  // [180, 1536]
    const float* Wk   = (const float*)d_in[3];  // [1536, 1536]
    float* out_s = (float*)d_out;                        // [4, 8192, 1536]
    float* out_w = out_s + (size_t)BB * RR * ATT_DIM;    // [4, 8192, 32]

    gemm1_kernel<<<dim3(ATT_DIM / 128, BB, KSPLIT), 256>>>(slot, Wk);
    reducek_kernel<<<(BB * ATT_DIM * SS / 4) / 256, 256>>>();
    gemm2_kernel<<<dim3((IN_DIM + 7) / 8, BB, ASPLIT), 256>>>(Wq);
    fused_kernel<<<dim3(RR / TILE_R, BB), 256>>>(x, slot, out_s, out_w);
}